// round 9
// baseline (speedup 1.0000x reference)
#include <cuda_runtime.h>
#include <cuda_fp16.h>
#include <cstdint>

#define B_   128
#define T_   512
#define E_   512
#define H_   1024
#define G3H_ 3072
#define NROW 65536   // B*T

#define NCTA 64      // CTAs in persistent recurrence
#define COLS 16      // h-columns per CTA
#define THR  512     // 16 warps: 8 M-slices x 2 K-halves
#define NKT  16      // stages per K-half (512/32)

// ---- recurrence SMEM layout (bytes) ----
#define WP_OFF   0            // packed fp16 weights: 12288 entries x 8B = 96KB
#define AS_OFF   98304        // 16 warps x 4 stages x 1280B = 80KB (reused as scratch)
#define ASTG     1280         // stage: 16 rows x (64B data + 16B pad)
#define AWARP    (4 * ASTG)
#define GX_OFF   180224       // 128 rows x 192B (48 fp32)
#define HOLD_OFF 204800       // 128 rows x 32B (16 fp16), persistent across steps
#define BIAS_OFF 208896       // 48 fp32
#define REC_SMEM 209152

#define GEMM_SMEM (3 * 2 * 128 * 20 * 4)

// ---------------- device scratch ----------------
__device__ __half g_x0 [(size_t)NROW * E_];
__device__ __half g_y0 [(size_t)NROW * H_];
__device__ float  g_gx0[(size_t)NROW * G3H_];
__device__ float  g_gx1[(size_t)NROW * G3H_];
__device__ __half g_wih0[G3H_ * E_];
__device__ __half g_wih1[G3H_ * H_];
__device__ __half g_h0[2][B_ * H_];
__device__ __half g_h1[2][B_ * H_];
__device__ unsigned g_flags0[NCTA * 32];
__device__ unsigned g_flags1[NCTA * 32];

// ---------------- helpers ----------------
__device__ __forceinline__ void cp16(void* s, const void* g) {
    uint32_t sa = (uint32_t)__cvta_generic_to_shared(s);
    asm volatile("cp.async.cg.shared.global [%0], [%1], 16;" :: "r"(sa), "l"(g));
}
__device__ __forceinline__ void cpcommit() { asm volatile("cp.async.commit_group;"); }

__device__ __forceinline__ void mma16(float c[4], const uint32_t a[4], const uint32_t b[2]) {
    asm volatile(
        "mma.sync.aligned.m16n8k16.row.col.f32.f16.f16.f32 "
        "{%0,%1,%2,%3}, {%4,%5,%6,%7}, {%8,%9}, {%0,%1,%2,%3};"
        : "+f"(c[0]), "+f"(c[1]), "+f"(c[2]), "+f"(c[3])
        : "r"(a[0]), "r"(a[1]), "r"(a[2]), "r"(a[3]), "r"(b[0]), "r"(b[1]));
}

__device__ __forceinline__ float tanh_ap(float x) {
    float y;
    asm("tanh.approx.f32 %0, %1;" : "=f"(y) : "f"(x));
    return y;
}
__device__ __forceinline__ float sigm_ap(float x) {
    return 0.5f + 0.5f * tanh_ap(0.5f * x);
}

// parallel-poll grid barrier: 1 writer, NCTA pollers (one flag each)
__device__ __forceinline__ void flag_barrier(unsigned* flags, int bid, int tid,
                                             unsigned target) {
    __syncthreads();
    if (tid == 0)
        asm volatile("st.release.gpu.global.u32 [%0], %1;"
                     :: "l"(flags + bid * 32), "r"(target) : "memory");
    if (tid < NCTA) {
        unsigned v;
        do {
            asm volatile("ld.acquire.gpu.global.u32 %0, [%1];"
                         : "=r"(v) : "l"(flags + tid * 32) : "memory");
        } while (v < target);
    }
    __syncthreads();
}

// ---------------- setup: fp16-convert wih, zero h, reset flags ----------------
__global__ void k_setup(const float* __restrict__ wih0, const float* __restrict__ wih1) {
    int stride = gridDim.x * blockDim.x;
    for (int i = blockIdx.x * blockDim.x + threadIdx.x; i < G3H_ * H_; i += stride) {
        if (i < G3H_ * E_) g_wih0[i] = __float2half_rn(wih0[i]);
        g_wih1[i] = __float2half_rn(wih1[i]);
        if (i < 2 * B_ * H_) {
            (&g_h0[0][0])[i] = __float2half_rn(0.f);
            (&g_h1[0][0])[i] = __float2half_rn(0.f);
        }
        if (i < NCTA * 32) { g_flags0[i] = 0u; g_flags1[i] = 0u; }
    }
}

__global__ void k_gather(const int* __restrict__ src, const float* __restrict__ emb,
                         __half* __restrict__ x0) {
    int row = blockIdx.x;
    int v = src[row];
    const float* e = emb + (size_t)v * E_;
    __half* o = x0 + (size_t)row * E_;
    for (int j = threadIdx.x; j < E_; j += blockDim.x) o[j] = __float2half_rn(e[j]);
}

// ---------------- big GEMM (fp16 m16n8k16): C[M,3072] = A[M,K]*W[3072,K]^T + bias ----------------
__device__ __forceinline__ void gemm_load(uint32_t* As, uint32_t* Ws,
                                          const __half* Ab, const __half* Wb,
                                          int K, int kt, int tid) {
    #pragma unroll
    for (int i = 0; i < 2; i++) {
        int id = tid + 256 * i;
        int r = id >> 2, s = id & 3;
        cp16(As + r * 20 + s * 4, Ab + (size_t)r * K + kt * 32 + s * 8);
        cp16(Ws + r * 20 + s * 4, Wb + (size_t)r * K + kt * 32 + s * 8);
    }
    cpcommit();
}

__global__ __launch_bounds__(256) void k_gemm(const __half* __restrict__ A,
                                              const __half* __restrict__ W,
                                              const float* __restrict__ bias,
                                              float* __restrict__ C, int K) {
    extern __shared__ uint32_t gsm[];
    int tid = threadIdx.x;
    int lane = tid & 31, wid = tid >> 5;
    int g = lane >> 2, tg = lane & 3;
    int wM = wid & 1, wN = wid >> 1;
    const __half* Ab = A + (size_t)blockIdx.y * 128 * K;
    const __half* Wb = W + (size_t)blockIdx.x * 128 * K;

    float c[4][4][4];
    #pragma unroll
    for (int i = 0; i < 4; i++)
        #pragma unroll
        for (int j = 0; j < 4; j++)
            #pragma unroll
            for (int e = 0; e < 4; e++) c[i][j][e] = 0.f;

    int KIT = K / 32;
    gemm_load(gsm, gsm + 2560, Ab, Wb, K, 0, tid);
    gemm_load(gsm + 5120, gsm + 5120 + 2560, Ab, Wb, K, 1, tid);

    for (int kt = 0; kt < KIT; kt++) {
        asm volatile("cp.async.wait_group 1;");
        __syncthreads();
        if (kt + 2 < KIT) {
            uint32_t* st = gsm + ((kt + 2) % 3) * 5120;
            gemm_load(st, st + 2560, Ab, Wb, K, kt + 2, tid);
        } else cpcommit();
        uint32_t* As = gsm + (kt % 3) * 5120;
        uint32_t* Ws = As + 2560;
        #pragma unroll
        for (int ch = 0; ch < 2; ch++) {
            int co = ch * 8;
            uint32_t a[4][4], b[4][2];
            #pragma unroll
            for (int mt = 0; mt < 4; mt++) {
                int r0 = wM * 64 + mt * 16 + g;
                a[mt][0] = As[r0 * 20 + co + tg];
                a[mt][1] = As[(r0 + 8) * 20 + co + tg];
                a[mt][2] = As[r0 * 20 + co + tg + 4];
                a[mt][3] = As[(r0 + 8) * 20 + co + tg + 4];
            }
            #pragma unroll
            for (int nt = 0; nt < 4; nt++) {
                int n0 = wN * 32 + nt * 8 + g;
                b[nt][0] = Ws[n0 * 20 + co + tg];
                b[nt][1] = Ws[n0 * 20 + co + tg + 4];
            }
            #pragma unroll
            for (int mt = 0; mt < 4; mt++)
                #pragma unroll
                for (int nt = 0; nt < 4; nt++) mma16(c[mt][nt], a[mt], b[nt]);
        }
        __syncthreads();
    }

    size_t row0 = (size_t)blockIdx.y * 128;
    int col0 = blockIdx.x * 128 + wN * 32;
    #pragma unroll
    for (int mt = 0; mt < 4; mt++)
        #pragma unroll
        for (int nt = 0; nt < 4; nt++)
            #pragma unroll
            for (int ep = 0; ep < 2; ep++) {
                size_t row = row0 + wM * 64 + mt * 16 + g + ep * 8;
                int col = col0 + nt * 8 + 2 * tg;
                float2 v;
                v.x = c[mt][nt][2 * ep]     + bias[col];
                v.y = c[mt][nt][2 * ep + 1] + bias[col + 1];
                *(float2*)&C[row * G3H_ + col] = v;
            }
}

// ---------------- persistent recurrence: 64 CTAs x 16 cols, 16 warps (8M x 2K) ----------------
__global__ __launch_bounds__(THR, 1) void k_rec_persist(
    const float* __restrict__ W,      // whh raw fp32 [3072][1024]
    const float* __restrict__ gx,     // [B][T][3H] fp32
    const float* __restrict__ bhh,    // [3H]
    __half* __restrict__ hbuf,        // [2][B*H] ping-pong fp16
    __half* __restrict__ yout,        // [B][T][H] fp16 or nullptr
    float* __restrict__ outf,         // [B][H] final hidden fp32
    unsigned* __restrict__ flags) {
    extern __shared__ char smc[];
    uint32_t* Wp  = (uint32_t*)(smc + WP_OFF);
    float*    gxs = (float*)(smc + GX_OFF);
    __half*   hds = (__half*)(smc + HOLD_OFF);
    float*    bhs = (float*)(smc + BIAS_OFF);
    float*    scr = (float*)(smc + AS_OFF);     // reuses stage region after drain

    int tid = threadIdx.x;
    int lane = tid & 31, wid = tid >> 5;
    int g = lane >> 2, tg = lane & 3;
    int wM = wid & 7;                  // batch slice (16 rows)
    int kh = wid >> 3;                 // K half
    int bid = blockIdx.x;
    int nb = bid * COLS;

    // pack resident weights: entry e = (k16*6 + nf)*32 + lane -> 2 words
    // n = nf*8 + (lane>>2); gate = n>>4, col = n&15; k = k16*16 + 2*(lane&3)
    for (int e = tid; e < 12288; e += THR) {
        int lane_ = e & 31;
        int r = e >> 5;
        int nf = r % 6;
        int k16 = r / 6;
        int n = nf * 8 + (lane_ >> 2);
        int grow = (n >> 4) * H_ + nb + (n & 15);
        int k = k16 * 16 + 2 * (lane_ & 3);
        const float* wr = W + (size_t)grow * H_;
        __half2 w0 = __floats2half2_rn(wr[k],     wr[k + 1]);
        __half2 w1 = __floats2half2_rn(wr[k + 8], wr[k + 9]);
        Wp[e * 2]     = *(uint32_t*)&w0;
        Wp[e * 2 + 1] = *(uint32_t*)&w1;
    }
    if (tid < 48) bhs[tid] = bhh[(tid >> 4) * H_ + nb + (tid & 15)];
    // zero persistent holds (h(0) = 0): 1024 words
    ((uint32_t*)hds)[tid * 2]     = 0u;
    ((uint32_t*)hds)[tid * 2 + 1] = 0u;
    __syncthreads();

    char* myA = smc + AS_OFF + wid * AWARP;
    // per-thread stage-load map: 2 chunks of 16B (16 rows x 64B per stage)
    int srcOff[2]; int dstOff[2];
    #pragma unroll
    for (int i = 0; i < 2; i++) {
        int ch = lane + 32 * i;
        int r = ch >> 2, cc = ch & 3;
        srcOff[i] = r * H_ + kh * 512 + cc * 8;     // fp16 elements (+ kt*32 at use)
        dstOff[i] = r * 80 + cc * 16;               // bytes within stage
    }

    for (int t = 0; t < T_; t++) {
        const __half* hin = hbuf + (size_t)(t & 1) * (B_ * H_);
        __half* hout = hbuf + (size_t)((t + 1) & 1) * (B_ * H_);
        const __half* hwarp = hin + (size_t)(wM * 16) * H_;

        float c[6][4];
        #pragma unroll
        for (int j = 0; j < 6; j++)
            #pragma unroll
            for (int e = 0; e < 4; e++) c[j][e] = 0.f;

        // group 0: stage 0 + gx tile
        {
            cp16(myA + dstOff[0], hwarp + srcOff[0]);
            cp16(myA + dstOff[1], hwarp + srcOff[1]);
            #pragma unroll
            for (int i = 0; i < 3; i++) {
                int idx = tid + THR * i;
                int row = idx / 12, j = idx % 12;
                cp16(smc + GX_OFF + row * 192 + j * 16,
                     gx + (size_t)row * (T_ * G3H_) + (size_t)t * G3H_
                        + (j >> 2) * H_ + nb + (j & 3) * 4);
            }
            cpcommit();
        }
        // groups 1,2: stages 1,2
        #pragma unroll
        for (int s = 1; s < 3; s++) {
            char* dst = myA + s * ASTG;
            cp16(dst + dstOff[0], hwarp + s * 32 + srcOff[0]);
            cp16(dst + dstOff[1], hwarp + s * 32 + srcOff[1]);
            cpcommit();
        }

        for (int kt = 0; kt < NKT; kt++) {
            asm volatile("cp.async.wait_group 2;");
            if (kt + 3 < NKT) {
                char* dst = myA + ((kt + 3) & 3) * ASTG;
                const __half* hsrc = hwarp + (kt + 3) * 32;
                cp16(dst + dstOff[0], hsrc + srcOff[0]);
                cp16(dst + dstOff[1], hsrc + srcOff[1]);
            }
            cpcommit();

            const uint32_t* A = (const uint32_t*)(myA + (kt & 3) * ASTG);
            #pragma unroll
            for (int c16 = 0; c16 < 2; c16++) {
                int co = c16 * 8;
                uint32_t a[4];
                a[0] = A[g * 20 + co + tg];
                a[1] = A[(g + 8) * 20 + co + tg];
                a[2] = A[g * 20 + co + tg + 4];
                a[3] = A[(g + 8) * 20 + co + tg + 4];
                int k16 = kh * 32 + kt * 2 + c16;
                #pragma unroll
                for (int nf = 0; nf < 6; nf++) {
                    uint2 bv = *(const uint2*)&Wp[((k16 * 6 + nf) * 32 + lane) * 2];
                    uint32_t b[2] = { bv.x, bv.y };
                    mma16(c[nf], a, b);
                }
            }
        }

        // drain, exchange K-half partials via scratch (overlaps dead stage region)
        asm volatile("cp.async.wait_group 0;");
        __syncthreads();
        if (kh == 1) {
            float4* s = (float4*)(scr + ((size_t)(wid - 8) * 32 + lane) * 24);
            #pragma unroll
            for (int nf = 0; nf < 6; nf++)
                s[nf] = make_float4(c[nf][0], c[nf][1], c[nf][2], c[nf][3]);
        }
        __syncthreads();

        if (kh == 0) {
            const float4* s = (const float4*)(scr + ((size_t)wid * 32 + lane) * 24);
            #pragma unroll
            for (int nf = 0; nf < 6; nf++) {
                float4 p = s[nf];
                c[nf][0] += p.x; c[nf][1] += p.y; c[nf][2] += p.z; c[nf][3] += p.w;
            }

            #pragma unroll
            for (int ep = 0; ep < 2; ep++) {
                int row = wM * 16 + g + ep * 8;
                const float* gxr = gxs + row * 48;
                __half* hrow_s = hds + row * 16;
                #pragma unroll
                for (int cg = 0; cg < 2; cg++) {
                    float2 hv;
                    #pragma unroll
                    for (int hf = 0; hf < 2; hf++) {
                        int e = ep * 2 + hf;
                        int col = cg * 8 + 2 * tg + hf;
                        float xr = gxr[col], xz = gxr[16 + col], xn = gxr[32 + col];
                        float hr = c[cg][e]     + bhs[col];
                        float hz = c[2 + cg][e] + bhs[16 + col];
                        float hn = c[4 + cg][e] + bhs[32 + col];
                        float rr = sigm_ap(xr + hr);
                        float zz = sigm_ap(xz + hz);
                        float nn = tanh_ap(xn + rr * hn);
                        float ho = __half2float(hrow_s[col]);
                        float hnew = (1.f - zz) * nn + zz * ho;
                        (hf ? hv.y : hv.x) = hnew;
                    }
                    int col0 = cg * 8 + 2 * tg;
                    __half2 hq = __floats2half2_rn(hv.x, hv.y);
                    *(__half2*)&hrow_s[col0] = hq;                       // persistent h_old
                    *(__half2*)&hout[(size_t)row * H_ + nb + col0] = hq;
                    if (yout)
                        *(__half2*)&yout[(size_t)row * (T_ * H_) + (size_t)t * H_ + nb + col0] = hq;
                    if (t == T_ - 1)
                        *(float2*)&outf[(size_t)row * H_ + nb + col0] = hv;
                }
            }
        }

        if (t != T_ - 1) flag_barrier(flags, bid, tid, (unsigned)(t + 1));
    }
}

// ---------------- launch ----------------
extern "C" void kernel_launch(void* const* d_in, const int* in_sizes, int n_in,
                              void* d_out, int out_size) {
    const int*   src  = (const int*)d_in[0];
    const float* emb  = (const float*)d_in[1];
    const float* wih0 = (const float*)d_in[2];
    const float* whh0 = (const float*)d_in[3];
    const float* bih0 = (const float*)d_in[4];
    const float* bhh0 = (const float*)d_in[5];
    const float* wih1 = (const float*)d_in[6];
    const float* whh1 = (const float*)d_in[7];
    const float* bih1 = (const float*)d_in[8];
    const float* bhh1 = (const float*)d_in[9];
    float* out = (float*)d_out;

    __half *x0, *y0, *pwih0, *pwih1, *h0, *h1;
    float *gx0, *gx1;
    unsigned *fl0, *fl1;
    cudaGetSymbolAddress((void**)&x0,    g_x0);
    cudaGetSymbolAddress((void**)&y0,    g_y0);
    cudaGetSymbolAddress((void**)&gx0,   g_gx0);
    cudaGetSymbolAddress((void**)&gx1,   g_gx1);
    cudaGetSymbolAddress((void**)&pwih0, g_wih0);
    cudaGetSymbolAddress((void**)&pwih1, g_wih1);
    cudaGetSymbolAddress((void**)&h0,    g_h0);
    cudaGetSymbolAddress((void**)&h1,    g_h1);
    cudaGetSymbolAddress((void**)&fl0,   g_flags0);
    cudaGetSymbolAddress((void**)&fl1,   g_flags1);

    cudaFuncSetAttribute(k_rec_persist, cudaFuncAttributeMaxDynamicSharedMemorySize, REC_SMEM);
    cudaFuncSetAttribute(k_gemm, cudaFuncAttributeMaxDynamicSharedMemorySize, GEMM_SMEM);

    // launch order keeps k_rec_persist at my-launch-index 3 for the ncu -s 5 window
    k_setup<<<2048, 256>>>(wih0, wih1);                                   // 0
    k_gather<<<NROW, 128>>>(src, emb, x0);                                // 1
    k_gemm<<<dim3(24, 512), 256, GEMM_SMEM>>>(x0, pwih0, bih0, gx0, E_);  // 2
    k_rec_persist<<<NCTA, THR, REC_SMEM>>>(whh0, gx0, bhh0, h0, y0, out, fl0);        // 3
    k_gemm<<<dim3(24, 512), 256, GEMM_SMEM>>>(y0, pwih1, bih1, gx1, H_);  // 4
    k_rec_persist<<<NCTA, THR, REC_SMEM>>>(whh1, gx1, bhh1, h1, nullptr, out + B_ * H_, fl1); // 5
}

// round 10
// speedup vs baseline: 1.2254x; 1.2254x over previous
#include <cuda_runtime.h>
#include <cuda_fp16.h>
#include <cstdint>

#define B_   128
#define T_   512
#define E_   512
#define H_   1024
#define G3H_ 3072
#define NROW 65536   // B*T

#define NCTA 128     // CTAs in persistent recurrence
#define COLS 8       // h-columns per CTA
#define THR  512     // 16 warps: 8 M-slices x 2 K-halves
#define NKT  8       // stages per K-half (512/64)

// ---- recurrence SMEM layout (bytes) ----
#define WP_OFF   0                       // packed fp16 weights: 6144 entries x 8B = 48KB
#define AS_OFF   49152                   // 16 warps x 3 stages x 2304B = 108KB
#define ASTG     2304                    // stage: 16 rows x (128B data + 16B pad)
#define AWARP    (3 * ASTG)
#define GX_OFF   159744                  // 2 buffers x 128 rows x 112B (24 fp32 + pad)
#define GX_ROWB  112
#define GX_BUF   14336
#define HOLD_OFF 188416                  // 128 rows x 16B (8 fp16), persistent
#define BIAS_OFF 190464                  // 24 fp32 (+pad)
#define SCR_OFF  190592                  // 256 threads x 12 fp32 partials
#define REC_SMEM (SCR_OFF + 12288)       // 202880

#define GEMM_SMEM (3 * 2 * 128 * 20 * 4)

// ---------------- device scratch ----------------
__device__ __half g_x0 [(size_t)NROW * E_];
__device__ __half g_y0 [(size_t)NROW * H_];
__device__ float  g_gx0[(size_t)NROW * G3H_];
__device__ float  g_gx1[(size_t)NROW * G3H_];
__device__ __half g_wih0[G3H_ * E_];
__device__ __half g_wih1[G3H_ * H_];
__device__ __half g_h0[2][B_ * H_];
__device__ __half g_h1[2][B_ * H_];
__device__ unsigned g_flags0[NCTA * 32];
__device__ unsigned g_flags1[NCTA * 32];

// ---------------- helpers ----------------
__device__ __forceinline__ void cp16(void* s, const void* g) {
    uint32_t sa = (uint32_t)__cvta_generic_to_shared(s);
    asm volatile("cp.async.cg.shared.global [%0], [%1], 16;" :: "r"(sa), "l"(g));
}
__device__ __forceinline__ void cpcommit() { asm volatile("cp.async.commit_group;"); }

__device__ __forceinline__ void mma16(float c[4], const uint32_t a[4], const uint32_t b[2]) {
    asm volatile(
        "mma.sync.aligned.m16n8k16.row.col.f32.f16.f16.f32 "
        "{%0,%1,%2,%3}, {%4,%5,%6,%7}, {%8,%9}, {%0,%1,%2,%3};"
        : "+f"(c[0]), "+f"(c[1]), "+f"(c[2]), "+f"(c[3])
        : "r"(a[0]), "r"(a[1]), "r"(a[2]), "r"(a[3]), "r"(b[0]), "r"(b[1]));
}

__device__ __forceinline__ float tanh_ap(float x) {
    float y;
    asm("tanh.approx.f32 %0, %1;" : "=f"(y) : "f"(x));
    return y;
}
__device__ __forceinline__ float sigm_ap(float x) {
    return 0.5f + 0.5f * tanh_ap(0.5f * x);
}

// parallel-poll grid barrier: 1 writer, NCTA pollers (one flag each)
__device__ __forceinline__ void flag_barrier(unsigned* flags, int bid, int tid,
                                             unsigned target) {
    __syncthreads();
    if (tid == 0)
        asm volatile("st.release.gpu.global.u32 [%0], %1;"
                     :: "l"(flags + bid * 32), "r"(target) : "memory");
    if (tid < NCTA) {
        unsigned v;
        do {
            asm volatile("ld.acquire.gpu.global.u32 %0, [%1];"
                         : "=r"(v) : "l"(flags + tid * 32) : "memory");
        } while (v < target);
    }
    __syncthreads();
}

// ---------------- setup: fp16-convert wih, zero h, reset flags ----------------
__global__ void k_setup(const float* __restrict__ wih0, const float* __restrict__ wih1) {
    int stride = gridDim.x * blockDim.x;
    for (int i = blockIdx.x * blockDim.x + threadIdx.x; i < G3H_ * H_; i += stride) {
        if (i < G3H_ * E_) g_wih0[i] = __float2half_rn(wih0[i]);
        g_wih1[i] = __float2half_rn(wih1[i]);
        if (i < 2 * B_ * H_) {
            (&g_h0[0][0])[i] = __float2half_rn(0.f);
            (&g_h1[0][0])[i] = __float2half_rn(0.f);
        }
        if (i < NCTA * 32) { g_flags0[i] = 0u; g_flags1[i] = 0u; }
    }
}

__global__ void k_gather(const int* __restrict__ src, const float* __restrict__ emb,
                         __half* __restrict__ x0) {
    int row = blockIdx.x;
    int v = src[row];
    const float* e = emb + (size_t)v * E_;
    __half* o = x0 + (size_t)row * E_;
    for (int j = threadIdx.x; j < E_; j += blockDim.x) o[j] = __float2half_rn(e[j]);
}

// ---------------- big GEMM (fp16 m16n8k16): C[M,3072] = A[M,K]*W[3072,K]^T + bias ----------------
__device__ __forceinline__ void gemm_load(uint32_t* As, uint32_t* Ws,
                                          const __half* Ab, const __half* Wb,
                                          int K, int kt, int tid) {
    #pragma unroll
    for (int i = 0; i < 2; i++) {
        int id = tid + 256 * i;
        int r = id >> 2, s = id & 3;
        cp16(As + r * 20 + s * 4, Ab + (size_t)r * K + kt * 32 + s * 8);
        cp16(Ws + r * 20 + s * 4, Wb + (size_t)r * K + kt * 32 + s * 8);
    }
    cpcommit();
}

__global__ __launch_bounds__(256) void k_gemm(const __half* __restrict__ A,
                                              const __half* __restrict__ W,
                                              const float* __restrict__ bias,
                                              float* __restrict__ C, int K) {
    extern __shared__ uint32_t gsm[];
    int tid = threadIdx.x;
    int lane = tid & 31, wid = tid >> 5;
    int g = lane >> 2, tg = lane & 3;
    int wM = wid & 1, wN = wid >> 1;
    const __half* Ab = A + (size_t)blockIdx.y * 128 * K;
    const __half* Wb = W + (size_t)blockIdx.x * 128 * K;

    float c[4][4][4];
    #pragma unroll
    for (int i = 0; i < 4; i++)
        #pragma unroll
        for (int j = 0; j < 4; j++)
            #pragma unroll
            for (int e = 0; e < 4; e++) c[i][j][e] = 0.f;

    int KIT = K / 32;
    gemm_load(gsm, gsm + 2560, Ab, Wb, K, 0, tid);
    gemm_load(gsm + 5120, gsm + 5120 + 2560, Ab, Wb, K, 1, tid);

    for (int kt = 0; kt < KIT; kt++) {
        asm volatile("cp.async.wait_group 1;");
        __syncthreads();
        if (kt + 2 < KIT) {
            uint32_t* st = gsm + ((kt + 2) % 3) * 5120;
            gemm_load(st, st + 2560, Ab, Wb, K, kt + 2, tid);
        } else cpcommit();
        uint32_t* As = gsm + (kt % 3) * 5120;
        uint32_t* Ws = As + 2560;
        #pragma unroll
        for (int ch = 0; ch < 2; ch++) {
            int co = ch * 8;
            uint32_t a[4][4], b[4][2];
            #pragma unroll
            for (int mt = 0; mt < 4; mt++) {
                int r0 = wM * 64 + mt * 16 + g;
                a[mt][0] = As[r0 * 20 + co + tg];
                a[mt][1] = As[(r0 + 8) * 20 + co + tg];
                a[mt][2] = As[r0 * 20 + co + tg + 4];
                a[mt][3] = As[(r0 + 8) * 20 + co + tg + 4];
            }
            #pragma unroll
            for (int nt = 0; nt < 4; nt++) {
                int n0 = wN * 32 + nt * 8 + g;
                b[nt][0] = Ws[n0 * 20 + co + tg];
                b[nt][1] = Ws[n0 * 20 + co + tg + 4];
            }
            #pragma unroll
            for (int mt = 0; mt < 4; mt++)
                #pragma unroll
                for (int nt = 0; nt < 4; nt++) mma16(c[mt][nt], a[mt], b[nt]);
        }
        __syncthreads();
    }

    size_t row0 = (size_t)blockIdx.y * 128;
    int col0 = blockIdx.x * 128 + wN * 32;
    #pragma unroll
    for (int mt = 0; mt < 4; mt++)
        #pragma unroll
        for (int nt = 0; nt < 4; nt++)
            #pragma unroll
            for (int ep = 0; ep < 2; ep++) {
                size_t row = row0 + wM * 64 + mt * 16 + g + ep * 8;
                int col = col0 + nt * 8 + 2 * tg;
                float2 v;
                v.x = c[mt][nt][2 * ep]     + bias[col];
                v.y = c[mt][nt][2 * ep + 1] + bias[col + 1];
                *(float2*)&C[row * G3H_ + col] = v;
            }
}

// ---------------- persistent recurrence: 128 CTAs x 8 cols, 16 warps (8M x 2K) ----------------
__global__ __launch_bounds__(THR, 1) void k_rec_persist(
    const float* __restrict__ W,      // whh raw fp32 [3072][1024]
    const float* __restrict__ gx,     // [B][T][3H] fp32
    const float* __restrict__ bhh,    // [3H]
    __half* __restrict__ hbuf,        // [2][B*H] ping-pong fp16
    __half* __restrict__ yout,        // [B][T][H] fp16 or nullptr
    float* __restrict__ outf,         // [B][H] final hidden fp32
    unsigned* __restrict__ flags) {
    extern __shared__ char smc[];
    uint32_t* Wp  = (uint32_t*)(smc + WP_OFF);
    __half*   hds = (__half*)(smc + HOLD_OFF);
    float*    bhs = (float*)(smc + BIAS_OFF);
    float*    scr = (float*)(smc + SCR_OFF);

    int tid = threadIdx.x;
    int lane = tid & 31, wid = tid >> 5;
    int g = lane >> 2, tg = lane & 3;
    int wM = wid & 7;                  // batch slice (16 rows)
    int kh = wid >> 3;                 // K half
    int bid = blockIdx.x;
    int nb = bid * COLS;

    // pack resident weights: entry e = (k16*3+gt)*32+lane -> 2 words
    for (int e = tid; e < 6144; e += THR) {
        int lane_ = e & 31;
        int r = e >> 5;
        int gt = r % 3;
        int k16 = r / 3;
        int n = gt * H_ + nb + (lane_ >> 2);
        int k = k16 * 16 + 2 * (lane_ & 3);
        const float* wr = W + (size_t)n * H_;
        __half2 w0 = __floats2half2_rn(wr[k],     wr[k + 1]);
        __half2 w1 = __floats2half2_rn(wr[k + 8], wr[k + 9]);
        Wp[e * 2]     = *(uint32_t*)&w0;
        Wp[e * 2 + 1] = *(uint32_t*)&w1;
    }
    if (tid < 24) bhs[tid] = bhh[(tid >> 3) * H_ + nb + (tid & 7)];
    ((uint32_t*)hds)[tid] = 0u;    // persistent holds = h(0) = 0 (512 words)
    __syncthreads();

    char* myA = smc + AS_OFF + wid * AWARP;
    // per-thread stage-load map: 4 chunks of 16B (16 rows x 128B per stage)
    int srcOff[4]; int dstOff[4];
    #pragma unroll
    for (int i = 0; i < 4; i++) {
        int ch = lane + 32 * i;
        int r = ch >> 3, cc = ch & 7;
        srcOff[i] = r * H_ + kh * 512 + cc * 8;     // fp16 elements
        dstOff[i] = r * 144 + cc * 16;              // bytes within stage
    }
    // gx load map: 768 16B chunks over 512 threads
    // chunk idx -> row=idx/6, part=idx%6 -> gate=part>>1, half=part&1

    // preload gx(0) into buffer 0 (own commit group)
    {
        #pragma unroll
        for (int i = 0; i < 2; i++) {
            int idx = tid + THR * i;
            if (idx < 768) {
                int row = idx / 6, part = idx % 6;
                cp16(smc + GX_OFF + row * GX_ROWB + (part >> 1) * 32 + (part & 1) * 16,
                     gx + (size_t)row * (T_ * G3H_) + (size_t)(part >> 1) * H_
                        + nb + (part & 1) * 4);
            }
        }
        cpcommit();
    }

    for (int t = 0; t < T_; t++) {
        const __half* hin = hbuf + (size_t)(t & 1) * (B_ * H_);
        __half* hout = hbuf + (size_t)((t + 1) & 1) * (B_ * H_);
        const __half* hwarp = hin + (size_t)(wM * 16) * H_;
        const float* gxs = (const float*)(smc + GX_OFF + (t & 1) * GX_BUF);

        float c[3][4];
        #pragma unroll
        for (int j = 0; j < 3; j++)
            #pragma unroll
            for (int e = 0; e < 4; e++) c[j][e] = 0.f;

        // stages 0,1 (one group each)
        #pragma unroll
        for (int s = 0; s < 2; s++) {
            char* dst = myA + s * ASTG;
            const __half* hsrc = hwarp + s * 64;
            #pragma unroll
            for (int i = 0; i < 4; i++)
                cp16(dst + dstOff[i], hsrc + srcOff[i]);
            cpcommit();
        }

        for (int kt = 0; kt < NKT; kt++) {
            asm volatile("cp.async.wait_group 1;");
            if (kt + 2 < NKT) {
                char* dst = myA + ((kt + 2) % 3) * ASTG;
                const __half* hsrc = hwarp + (kt + 2) * 64;
                #pragma unroll
                for (int i = 0; i < 4; i++)
                    cp16(dst + dstOff[i], hsrc + srcOff[i]);
            }
            cpcommit();

            const uint32_t* A = (const uint32_t*)(myA + (kt % 3) * ASTG);
            #pragma unroll
            for (int c16 = 0; c16 < 4; c16++) {
                int co = c16 * 8;
                uint32_t a[4];
                a[0] = A[g * 36 + co + tg];
                a[1] = A[(g + 8) * 36 + co + tg];
                a[2] = A[g * 36 + co + tg + 4];
                a[3] = A[(g + 8) * 36 + co + tg + 4];
                int k16 = kh * 32 + kt * 4 + c16;
                #pragma unroll
                for (int gt = 0; gt < 3; gt++) {
                    uint2 bv = *(const uint2*)&Wp[((k16 * 3 + gt) * 32 + lane) * 2];
                    uint32_t b[2] = { bv.x, bv.y };
                    mma16(c[gt], a, b);
                }
            }
        }

        // drain, exchange K-half partials through scratch
        asm volatile("cp.async.wait_group 0;");
        __syncthreads();
        if (kh == 1) {
            float4* s = (float4*)(scr + ((size_t)(wid - 8) * 32 + lane) * 12);
            s[0] = make_float4(c[0][0], c[0][1], c[0][2], c[0][3]);
            s[1] = make_float4(c[1][0], c[1][1], c[1][2], c[1][3]);
            s[2] = make_float4(c[2][0], c[2][1], c[2][2], c[2][3]);
        }
        __syncthreads();

        if (kh == 0) {
            const float4* s = (const float4*)(scr + ((size_t)wid * 32 + lane) * 12);
            float4 p0 = s[0], p1 = s[1], p2 = s[2];
            c[0][0] += p0.x; c[0][1] += p0.y; c[0][2] += p0.z; c[0][3] += p0.w;
            c[1][0] += p1.x; c[1][1] += p1.y; c[1][2] += p1.z; c[1][3] += p1.w;
            c[2][0] += p2.x; c[2][1] += p2.y; c[2][2] += p2.z; c[2][3] += p2.w;

            #pragma unroll
            for (int ep = 0; ep < 2; ep++) {
                int row = wM * 16 + g + ep * 8;
                const float* gxr = gxs + row * 28;
                __half* hrow_s = hds + row * 8;
                float2 hv;
                #pragma unroll
                for (int hf = 0; hf < 2; hf++) {
                    int e = 2 * ep + hf;
                    int lc = 2 * tg + hf;
                    float xr = gxr[lc], xz = gxr[8 + lc], xn = gxr[16 + lc];
                    float hr = c[0][e] + bhs[lc];
                    float hz = c[1][e] + bhs[8 + lc];
                    float hn = c[2][e] + bhs[16 + lc];
                    float rr = sigm_ap(xr + hr);
                    float zz = sigm_ap(xz + hz);
                    float nn = tanh_ap(xn + rr * hn);
                    float ho = __half2float(hrow_s[lc]);
                    float hnew = (1.f - zz) * nn + zz * ho;
                    (hf ? hv.y : hv.x) = hnew;
                }
                int col = nb + 2 * tg;
                __half2 hq = __floats2half2_rn(hv.x, hv.y);
                *(__half2*)&hrow_s[2 * tg] = hq;                 // persistent h_old
                *(__half2*)&hout[(size_t)row * H_ + col] = hq;
                if (yout)
                    *(__half2*)&yout[(size_t)row * (T_ * H_) + (size_t)t * H_ + col] = hq;
                if (t == T_ - 1) *(float2*)&outf[(size_t)row * H_ + col] = hv;
            }
        }

        // prefetch gx(t+1) into the other buffer; overlaps the grid barrier
        if (t + 1 < T_) {
            char* gdst = smc + GX_OFF + ((t + 1) & 1) * GX_BUF;
            #pragma unroll
            for (int i = 0; i < 2; i++) {
                int idx = tid + THR * i;
                if (idx < 768) {
                    int row = idx / 6, part = idx % 6;
                    cp16(gdst + row * GX_ROWB + (part >> 1) * 32 + (part & 1) * 16,
                         gx + (size_t)row * (T_ * G3H_) + (size_t)(t + 1) * G3H_
                            + (part >> 1) * H_ + nb + (part & 1) * 4);
                }
            }
            cpcommit();
            flag_barrier(flags, bid, tid, (unsigned)(t + 1));
        }
    }
}

// ---------------- launch ----------------
extern "C" void kernel_launch(void* const* d_in, const int* in_sizes, int n_in,
                              void* d_out, int out_size) {
    const int*   src  = (const int*)d_in[0];
    const float* emb  = (const float*)d_in[1];
    const float* wih0 = (const float*)d_in[2];
    const float* whh0 = (const float*)d_in[3];
    const float* bih0 = (const float*)d_in[4];
    const float* bhh0 = (const float*)d_in[5];
    const float* wih1 = (const float*)d_in[6];
    const float* whh1 = (const float*)d_in[7];
    const float* bih1 = (const float*)d_in[8];
    const float* bhh1 = (const float*)d_in[9];
    float* out = (float*)d_out;

    __half *x0, *y0, *pwih0, *pwih1, *h0, *h1;
    float *gx0, *gx1;
    unsigned *fl0, *fl1;
    cudaGetSymbolAddress((void**)&x0,    g_x0);
    cudaGetSymbolAddress((void**)&y0,    g_y0);
    cudaGetSymbolAddress((void**)&gx0,   g_gx0);
    cudaGetSymbolAddress((void**)&gx1,   g_gx1);
    cudaGetSymbolAddress((void**)&pwih0, g_wih0);
    cudaGetSymbolAddress((void**)&pwih1, g_wih1);
    cudaGetSymbolAddress((void**)&h0,    g_h0);
    cudaGetSymbolAddress((void**)&h1,    g_h1);
    cudaGetSymbolAddress((void**)&fl0,   g_flags0);
    cudaGetSymbolAddress((void**)&fl1,   g_flags1);

    cudaFuncSetAttribute(k_rec_persist, cudaFuncAttributeMaxDynamicSharedMemorySize, REC_SMEM);
    cudaFuncSetAttribute(k_gemm, cudaFuncAttributeMaxDynamicSharedMemorySize, GEMM_SMEM);

    // launch order keeps k_rec_persist at my-launch-index 3 for the ncu -s 5 window
    k_setup<<<2048, 256>>>(wih0, wih1);                                   // 0
    k_gather<<<NROW, 128>>>(src, emb, x0);                                // 1
    k_gemm<<<dim3(24, 512), 256, GEMM_SMEM>>>(x0, pwih0, bih0, gx0, E_);  // 2
    k_rec_persist<<<NCTA, THR, REC_SMEM>>>(whh0, gx0, bhh0, h0, y0, out, fl0);        // 3
    k_gemm<<<dim3(24, 512), 256, GEMM_SMEM>>>(y0, pwih1, bih1, gx1, H_);  // 4
    k_rec_persist<<<NCTA, THR, REC_SMEM>>>(whh1, gx1, bhh1, h1, nullptr, out + B_ * H_, fl1); // 5
}

// round 11
// speedup vs baseline: 1.2576x; 1.0263x over previous
#include <cuda_runtime.h>
#include <cuda_fp16.h>
#include <cstdint>

#define B_   128
#define T_   512
#define E_   512
#define H_   1024
#define G3H_ 3072
#define NROW 65536   // B*T

#define NCTA 128     // CTAs in persistent recurrence
#define COLS 8       // h-columns per CTA
#define THR  512     // 16 warps: 8 M-slices x 2 K-halves
#define NKT  8       // stages per K-half (512/64)

// ---- recurrence SMEM layout (bytes) ----
#define WP_OFF   0                       // packed fp16 weights: 6144 entries x 8B = 48KB
#define AS_OFF   49152                   // 16 warps x 3 stages x 2304B = 108KB
#define ASTG     2304                    // stage: 16 rows x (128B data + 16B pad)
#define AWARP    (3 * ASTG)
#define GX_OFF   159744                  // 2 buffers x 128 rows x 112B (24 fp32 + pad)
#define GX_ROWB  112
#define GX_BUF   14336
#define HOLD_OFF 188416                  // 128 rows x 16B (8 fp16), persistent
#define BIAS_OFF 190464                  // 24 fp32 (+pad)
#define SCR_OFF  190592                  // 256 threads x 12 fp32 partials
#define REC_SMEM (SCR_OFF + 12288)       // 202880

#define GEMM_SMEM (3 * 2 * 128 * 20 * 4)

// ---------------- device scratch ----------------
__device__ __half g_x0 [(size_t)NROW * E_];
__device__ __half g_y0 [(size_t)NROW * H_];
__device__ float  g_gx0[(size_t)NROW * G3H_];
__device__ float  g_gx1[(size_t)NROW * G3H_];
__device__ __half g_wih0[G3H_ * E_];
__device__ __half g_wih1[G3H_ * H_];
__device__ __half g_h0[2][B_ * H_];
__device__ __half g_h1[2][B_ * H_];
__device__ unsigned g_flags0[NCTA * 32];
__device__ unsigned g_flags1[NCTA * 32];

// ---------------- helpers ----------------
__device__ __forceinline__ void cp16(void* s, const void* g) {
    uint32_t sa = (uint32_t)__cvta_generic_to_shared(s);
    asm volatile("cp.async.cg.shared.global [%0], [%1], 16;" :: "r"(sa), "l"(g));
}
__device__ __forceinline__ void cpcommit() { asm volatile("cp.async.commit_group;"); }

__device__ __forceinline__ void mma16(float c[4], const uint32_t a[4], const uint32_t b[2]) {
    asm volatile(
        "mma.sync.aligned.m16n8k16.row.col.f32.f16.f16.f32 "
        "{%0,%1,%2,%3}, {%4,%5,%6,%7}, {%8,%9}, {%0,%1,%2,%3};"
        : "+f"(c[0]), "+f"(c[1]), "+f"(c[2]), "+f"(c[3])
        : "r"(a[0]), "r"(a[1]), "r"(a[2]), "r"(a[3]), "r"(b[0]), "r"(b[1]));
}

__device__ __forceinline__ void ldsm4(uint32_t a[4], uint32_t addr) {
    asm volatile("ldmatrix.sync.aligned.m8n8.x4.shared.b16 {%0,%1,%2,%3}, [%4];"
                 : "=r"(a[0]), "=r"(a[1]), "=r"(a[2]), "=r"(a[3]) : "r"(addr));
}

__device__ __forceinline__ float tanh_ap(float x) {
    float y;
    asm("tanh.approx.f32 %0, %1;" : "=f"(y) : "f"(x));
    return y;
}
__device__ __forceinline__ float sigm_ap(float x) {
    return 0.5f + 0.5f * tanh_ap(0.5f * x);
}

// parallel-poll grid barrier: 1 writer, NCTA pollers (one flag each)
__device__ __forceinline__ void flag_barrier(unsigned* flags, int bid, int tid,
                                             unsigned target) {
    __syncthreads();
    if (tid == 0)
        asm volatile("st.release.gpu.global.u32 [%0], %1;"
                     :: "l"(flags + bid * 32), "r"(target) : "memory");
    if (tid < NCTA) {
        unsigned v;
        do {
            asm volatile("ld.acquire.gpu.global.u32 %0, [%1];"
                         : "=r"(v) : "l"(flags + tid * 32) : "memory");
        } while (v < target);
    }
    __syncthreads();
}

// ---------------- setup: fp16-convert wih, zero h, reset flags ----------------
__global__ void k_setup(const float* __restrict__ wih0, const float* __restrict__ wih1) {
    int stride = gridDim.x * blockDim.x;
    for (int i = blockIdx.x * blockDim.x + threadIdx.x; i < G3H_ * H_; i += stride) {
        if (i < G3H_ * E_) g_wih0[i] = __float2half_rn(wih0[i]);
        g_wih1[i] = __float2half_rn(wih1[i]);
        if (i < 2 * B_ * H_) {
            (&g_h0[0][0])[i] = __float2half_rn(0.f);
            (&g_h1[0][0])[i] = __float2half_rn(0.f);
        }
        if (i < NCTA * 32) { g_flags0[i] = 0u; g_flags1[i] = 0u; }
    }
}

__global__ void k_gather(const int* __restrict__ src, const float* __restrict__ emb,
                         __half* __restrict__ x0) {
    int row = blockIdx.x;
    int v = src[row];
    const float* e = emb + (size_t)v * E_;
    __half* o = x0 + (size_t)row * E_;
    for (int j = threadIdx.x; j < E_; j += blockDim.x) o[j] = __float2half_rn(e[j]);
}

// ---------------- big GEMM (fp16 m16n8k16): C[M,3072] = A[M,K]*W[3072,K]^T + bias ----------------
__device__ __forceinline__ void gemm_load(uint32_t* As, uint32_t* Ws,
                                          const __half* Ab, const __half* Wb,
                                          int K, int kt, int tid) {
    #pragma unroll
    for (int i = 0; i < 2; i++) {
        int id = tid + 256 * i;
        int r = id >> 2, s = id & 3;
        cp16(As + r * 20 + s * 4, Ab + (size_t)r * K + kt * 32 + s * 8);
        cp16(Ws + r * 20 + s * 4, Wb + (size_t)r * K + kt * 32 + s * 8);
    }
    cpcommit();
}

__global__ __launch_bounds__(256) void k_gemm(const __half* __restrict__ A,
                                              const __half* __restrict__ W,
                                              const float* __restrict__ bias,
                                              float* __restrict__ C, int K) {
    extern __shared__ uint32_t gsm[];
    int tid = threadIdx.x;
    int lane = tid & 31, wid = tid >> 5;
    int g = lane >> 2, tg = lane & 3;
    int wM = wid & 1, wN = wid >> 1;
    const __half* Ab = A + (size_t)blockIdx.y * 128 * K;
    const __half* Wb = W + (size_t)blockIdx.x * 128 * K;

    float c[4][4][4];
    #pragma unroll
    for (int i = 0; i < 4; i++)
        #pragma unroll
        for (int j = 0; j < 4; j++)
            #pragma unroll
            for (int e = 0; e < 4; e++) c[i][j][e] = 0.f;

    int KIT = K / 32;
    gemm_load(gsm, gsm + 2560, Ab, Wb, K, 0, tid);
    gemm_load(gsm + 5120, gsm + 5120 + 2560, Ab, Wb, K, 1, tid);

    for (int kt = 0; kt < KIT; kt++) {
        asm volatile("cp.async.wait_group 1;");
        __syncthreads();
        if (kt + 2 < KIT) {
            uint32_t* st = gsm + ((kt + 2) % 3) * 5120;
            gemm_load(st, st + 2560, Ab, Wb, K, kt + 2, tid);
        } else cpcommit();
        uint32_t* As = gsm + (kt % 3) * 5120;
        uint32_t* Ws = As + 2560;
        #pragma unroll
        for (int ch = 0; ch < 2; ch++) {
            int co = ch * 8;
            uint32_t a[4][4], b[4][2];
            #pragma unroll
            for (int mt = 0; mt < 4; mt++) {
                int r0 = wM * 64 + mt * 16 + g;
                a[mt][0] = As[r0 * 20 + co + tg];
                a[mt][1] = As[(r0 + 8) * 20 + co + tg];
                a[mt][2] = As[r0 * 20 + co + tg + 4];
                a[mt][3] = As[(r0 + 8) * 20 + co + tg + 4];
            }
            #pragma unroll
            for (int nt = 0; nt < 4; nt++) {
                int n0 = wN * 32 + nt * 8 + g;
                b[nt][0] = Ws[n0 * 20 + co + tg];
                b[nt][1] = Ws[n0 * 20 + co + tg + 4];
            }
            #pragma unroll
            for (int mt = 0; mt < 4; mt++)
                #pragma unroll
                for (int nt = 0; nt < 4; nt++) mma16(c[mt][nt], a[mt], b[nt]);
        }
        // no bottom __syncthreads: with 3 stages + wait_group 1, writers of slot
        // (kt+2)%3 are post-top-bar and readers of the aliased slot pre-top-bar
    }

    size_t row0 = (size_t)blockIdx.y * 128;
    int col0 = blockIdx.x * 128 + wN * 32;
    #pragma unroll
    for (int mt = 0; mt < 4; mt++)
        #pragma unroll
        for (int nt = 0; nt < 4; nt++)
            #pragma unroll
            for (int ep = 0; ep < 2; ep++) {
                size_t row = row0 + wM * 64 + mt * 16 + g + ep * 8;
                int col = col0 + nt * 8 + 2 * tg;
                float2 v;
                v.x = c[mt][nt][2 * ep]     + bias[col];
                v.y = c[mt][nt][2 * ep + 1] + bias[col + 1];
                *(float2*)&C[row * G3H_ + col] = v;
            }
}

// ---------------- persistent recurrence: 128 CTAs x 8 cols, 16 warps (8M x 2K) ----------------
__global__ __launch_bounds__(THR, 1) void k_rec_persist(
    const float* __restrict__ W,      // whh raw fp32 [3072][1024]
    const float* __restrict__ gx,     // [B][T][3H] fp32
    const float* __restrict__ bhh,    // [3H]
    __half* __restrict__ hbuf,        // [2][B*H] ping-pong fp16
    __half* __restrict__ yout,        // [B][T][H] fp16 or nullptr
    float* __restrict__ outf,         // [B][H] final hidden fp32
    unsigned* __restrict__ flags) {
    extern __shared__ char smc[];
    uint32_t* Wp  = (uint32_t*)(smc + WP_OFF);
    __half*   hds = (__half*)(smc + HOLD_OFF);
    float*    bhs = (float*)(smc + BIAS_OFF);
    float*    scr = (float*)(smc + SCR_OFF);

    int tid = threadIdx.x;
    int lane = tid & 31, wid = tid >> 5;
    int g = lane >> 2, tg = lane & 3;
    int wM = wid & 7;                  // batch slice (16 rows)
    int kh = wid >> 3;                 // K half
    int bid = blockIdx.x;
    int nb = bid * COLS;

    // pack resident weights: entry e = (k16*3+gt)*32+lane -> 2 words
    for (int e = tid; e < 6144; e += THR) {
        int lane_ = e & 31;
        int r = e >> 5;
        int gt = r % 3;
        int k16 = r / 3;
        int n = gt * H_ + nb + (lane_ >> 2);
        int k = k16 * 16 + 2 * (lane_ & 3);
        const float* wr = W + (size_t)n * H_;
        __half2 w0 = __floats2half2_rn(wr[k],     wr[k + 1]);
        __half2 w1 = __floats2half2_rn(wr[k + 8], wr[k + 9]);
        Wp[e * 2]     = *(uint32_t*)&w0;
        Wp[e * 2 + 1] = *(uint32_t*)&w1;
    }
    if (tid < 24) bhs[tid] = bhh[(tid >> 3) * H_ + nb + (tid & 7)];
    ((uint32_t*)hds)[tid] = 0u;    // persistent holds = h(0) = 0 (512 words)
    __syncthreads();

    char* myA = smc + AS_OFF + wid * AWARP;
    // ldmatrix base: lanes 0-7 rows0-7 kLo, 8-15 rows8-15 kLo, 16-23 rows0-7 kHi, 24-31 rows8-15 kHi
    uint32_t aLdsm = (uint32_t)__cvta_generic_to_shared(myA)
                   + (uint32_t)(lane & 15) * 144 + (uint32_t)(lane >> 4) * 16;

    // per-thread stage-load map: 4 chunks of 16B (16 rows x 128B per stage)
    int srcOff[4]; int dstOff[4];
    #pragma unroll
    for (int i = 0; i < 4; i++) {
        int ch = lane + 32 * i;
        int r = ch >> 3, cc = ch & 7;
        srcOff[i] = r * H_ + kh * 512 + cc * 8;     // fp16 elements
        dstOff[i] = r * 144 + cc * 16;              // bytes within stage
    }

    // preload gx(0) into buffer 0 (kh==1 threads only; own commit group)
    if (kh == 1) {
        #pragma unroll
        for (int i = 0; i < 3; i++) {
            int idx = (tid - 256) + 256 * i;
            int row = idx / 6, part = idx % 6;
            cp16(smc + GX_OFF + row * GX_ROWB + (part >> 1) * 32 + (part & 1) * 16,
                 gx + (size_t)row * (T_ * G3H_) + (size_t)(part >> 1) * H_
                    + nb + (part & 1) * 4);
        }
        cpcommit();
    }

    for (int t = 0; t < T_; t++) {
        const __half* hin = hbuf + (size_t)(t & 1) * (B_ * H_);
        __half* hout = hbuf + (size_t)((t + 1) & 1) * (B_ * H_);
        const __half* hwarp = hin + (size_t)(wM * 16) * H_;
        const float* gxs = (const float*)(smc + GX_OFF + (t & 1) * GX_BUF);

        float c[3][4];
        #pragma unroll
        for (int j = 0; j < 3; j++)
            #pragma unroll
            for (int e = 0; e < 4; e++) c[j][e] = 0.f;

        // stages 0,1 (one group each)
        #pragma unroll
        for (int s = 0; s < 2; s++) {
            char* dst = myA + s * ASTG;
            const __half* hsrc = hwarp + s * 64;
            #pragma unroll
            for (int i = 0; i < 4; i++)
                cp16(dst + dstOff[i], hsrc + srcOff[i]);
            cpcommit();
        }

        for (int kt = 0; kt < NKT; kt++) {
            asm volatile("cp.async.wait_group 1;");
            if (kt + 2 < NKT) {
                char* dst = myA + ((kt + 2) % 3) * ASTG;
                const __half* hsrc = hwarp + (kt + 2) * 64;
                #pragma unroll
                for (int i = 0; i < 4; i++)
                    cp16(dst + dstOff[i], hsrc + srcOff[i]);
            }
            cpcommit();

            uint32_t stAddr = aLdsm + (uint32_t)((kt % 3) * ASTG);
            #pragma unroll
            for (int c16 = 0; c16 < 4; c16++) {
                uint32_t a[4];
                ldsm4(a, stAddr + (uint32_t)c16 * 32);
                int k16 = kh * 32 + kt * 4 + c16;
                #pragma unroll
                for (int gt = 0; gt < 3; gt++) {
                    uint2 bv = *(const uint2*)&Wp[((k16 * 3 + gt) * 32 + lane) * 2];
                    uint32_t b[2] = { bv.x, bv.y };
                    mma16(c[gt], a, b);
                }
            }
        }

        // drain; kh==1 writes partials + prefetches gx(t+1); one bar; kh==0 epilogue
        asm volatile("cp.async.wait_group 0;");
        if (kh == 1) {
            float4* s = (float4*)(scr + ((size_t)(wid - 8) * 32 + lane) * 12);
            s[0] = make_float4(c[0][0], c[0][1], c[0][2], c[0][3]);
            s[1] = make_float4(c[1][0], c[1][1], c[1][2], c[1][3]);
            s[2] = make_float4(c[2][0], c[2][1], c[2][2], c[2][3]);
            if (t + 1 < T_) {
                char* gdst = smc + GX_OFF + ((t + 1) & 1) * GX_BUF;
                #pragma unroll
                for (int i = 0; i < 3; i++) {
                    int idx = (tid - 256) + 256 * i;
                    int row = idx / 6, part = idx % 6;
                    cp16(gdst + row * GX_ROWB + (part >> 1) * 32 + (part & 1) * 16,
                         gx + (size_t)row * (T_ * G3H_) + (size_t)(t + 1) * G3H_
                            + (part >> 1) * H_ + nb + (part & 1) * 4);
                }
                cpcommit();
            }
        }
        __syncthreads();

        if (kh == 0) {
            const float4* s = (const float4*)(scr + ((size_t)wid * 32 + lane) * 12);
            float4 p0 = s[0], p1 = s[1], p2 = s[2];
            c[0][0] += p0.x; c[0][1] += p0.y; c[0][2] += p0.z; c[0][3] += p0.w;
            c[1][0] += p1.x; c[1][1] += p1.y; c[1][2] += p1.z; c[1][3] += p1.w;
            c[2][0] += p2.x; c[2][1] += p2.y; c[2][2] += p2.z; c[2][3] += p2.w;

            #pragma unroll
            for (int ep = 0; ep < 2; ep++) {
                int row = wM * 16 + g + ep * 8;
                const float* gxr = gxs + row * 28;
                __half* hrow_s = hds + row * 8;
                float2 hv;
                #pragma unroll
                for (int hf = 0; hf < 2; hf++) {
                    int e = 2 * ep + hf;
                    int lc = 2 * tg + hf;
                    float xr = gxr[lc], xz = gxr[8 + lc], xn = gxr[16 + lc];
                    float hr = c[0][e] + bhs[lc];
                    float hz = c[1][e] + bhs[8 + lc];
                    float hn = c[2][e] + bhs[16 + lc];
                    float rr = sigm_ap(xr + hr);
                    float zz = sigm_ap(xz + hz);
                    float nn = tanh_ap(xn + rr * hn);
                    float ho = __half2float(hrow_s[lc]);
                    float hnew = (1.f - zz) * nn + zz * ho;
                    (hf ? hv.y : hv.x) = hnew;
                }
                int col = nb + 2 * tg;
                __half2 hq = __floats2half2_rn(hv.x, hv.y);
                *(__half2*)&hrow_s[2 * tg] = hq;                 // persistent h_old
                *(__half2*)&hout[(size_t)row * H_ + col] = hq;
                if (yout)
                    *(__half2*)&yout[(size_t)row * (T_ * H_) + (size_t)t * H_ + col] = hq;
                if (t == T_ - 1) *(float2*)&outf[(size_t)row * H_ + col] = hv;
            }
        }

        if (t + 1 < T_) flag_barrier(flags, bid, tid, (unsigned)(t + 1));
    }
}

// ---------------- launch ----------------
extern "C" void kernel_launch(void* const* d_in, const int* in_sizes, int n_in,
                              void* d_out, int out_size) {
    const int*   src  = (const int*)d_in[0];
    const float* emb  = (const float*)d_in[1];
    const float* wih0 = (const float*)d_in[2];
    const float* whh0 = (const float*)d_in[3];
    const float* bih0 = (const float*)d_in[4];
    const float* bhh0 = (const float*)d_in[5];
    const float* wih1 = (const float*)d_in[6];
    const float* whh1 = (const float*)d_in[7];
    const float* bih1 = (const float*)d_in[8];
    const float* bhh1 = (const float*)d_in[9];
    float* out = (float*)d_out;

    __half *x0, *y0, *pwih0, *pwih1, *h0, *h1;
    float *gx0, *gx1;
    unsigned *fl0, *fl1;
    cudaGetSymbolAddress((void**)&x0,    g_x0);
    cudaGetSymbolAddress((void**)&y0,    g_y0);
    cudaGetSymbolAddress((void**)&gx0,   g_gx0);
    cudaGetSymbolAddress((void**)&gx1,   g_gx1);
    cudaGetSymbolAddress((void**)&pwih0, g_wih0);
    cudaGetSymbolAddress((void**)&pwih1, g_wih1);
    cudaGetSymbolAddress((void**)&h0,    g_h0);
    cudaGetSymbolAddress((void**)&h1,    g_h1);
    cudaGetSymbolAddress((void**)&fl0,   g_flags0);
    cudaGetSymbolAddress((void**)&fl1,   g_flags1);

    cudaFuncSetAttribute(k_rec_persist, cudaFuncAttributeMaxDynamicSharedMemorySize, REC_SMEM);
    cudaFuncSetAttribute(k_gemm, cudaFuncAttributeMaxDynamicSharedMemorySize, GEMM_SMEM);

    // launch order keeps k_rec_persist at my-launch-index 3 for the ncu -s 5 window
    k_setup<<<2048, 256>>>(wih0, wih1);                                   // 0
    k_gather<<<NROW, 128>>>(src, emb, x0);                                // 1
    k_gemm<<<dim3(24, 512), 256, GEMM_SMEM>>>(x0, pwih0, bih0, gx0, E_);  // 2
    k_rec_persist<<<NCTA, THR, REC_SMEM>>>(whh0, gx0, bhh0, h0, y0, out, fl0);        // 3
    k_gemm<<<dim3(24, 512), 256, GEMM_SMEM>>>(y0, pwih1, bih1, gx1, H_);  // 4
    k_rec_persist<<<NCTA, THR, REC_SMEM>>>(whh1, gx1, bhh1, h1, nullptr, out + B_ * H_, fl1); // 5
}